// round 1
// baseline (speedup 1.0000x reference)
#include <cuda_runtime.h>
#include <math_constants.h>

#define BB 16
#define HH 50
#define SS 256
#define DD 256
#define KK 32
#define SM1 (SS - 1)   // 255

__global__ __launch_bounds__(256, 4)
void matching_reducer_kernel(
    const float* __restrict__ sel,   // (B,H,S,D) news_selection_embedding
    const float* __restrict__ txt,   // (B,H,S,D) news_embedding
    const float* __restrict__ user,  // (B,1,D)   user_repr
    const float* __restrict__ am,    // (B,H,S)   his_attn_mask
    const int*   __restrict__ rm,    // (B,H,S)   his_refined_mask
    const float* __restrict__ seg,   // (H,1,D)   segment_embedding
    float* __restrict__ out_terms,   // (B, H*K, D)
    float* __restrict__ out_mask,    // (B, H*K)
    float* __restrict__ out_kid)     // (B, H, K) as float
{
    const int bh  = blockIdx.x;          // 0..B*H-1
    const int b   = bh / HH;
    const int h   = bh % HH;
    const int tid = threadIdx.x;         // 0..255
    const int wid = tid >> 5;            // 0..7
    const int lane = tid & 31;

    __shared__ float qn[DD];             // normalized query
    __shared__ float sseg[DD];           // segment embedding for this h
    __shared__ float scores[SM1 + 1];
    __shared__ float red_val[8];
    __shared__ int   red_idx[8];
    __shared__ float sel_score[KK];
    __shared__ int   sel_idx[KK];
    __shared__ float sw[KK];
    __shared__ float wss[8];

    // ---- Phase 1: normalize user_repr[b] into smem; stage segment emb ----
    float qv = user[(size_t)b * DD + tid];
    sseg[tid] = seg[(size_t)h * DD + tid];
    float ssq = qv * qv;
    #pragma unroll
    for (int o = 16; o; o >>= 1) ssq += __shfl_xor_sync(0xffffffffu, ssq, o);
    if (lane == 0) wss[wid] = ssq;
    __syncthreads();
    if (tid == 0) {
        float t = 0.f;
        #pragma unroll
        for (int i = 0; i < 8; i++) t += wss[i];
        wss[0] = 1.0f / fmaxf(sqrtf(t), 1e-12f);
    }
    __syncthreads();
    const float qscale = wss[0];
    qn[tid] = qv * qscale;
    __syncthreads();

    // ---- Phase 2: cosine scores for rows s=1..255 (one warp per row) ----
    const float* selbase = sel + (size_t)bh * SS * DD;
    const int*   rmbase  = rm  + (size_t)bh * SS;
    const float4* q4 = reinterpret_cast<const float4*>(qn);
    const float4 q0 = q4[lane];
    const float4 q1 = q4[lane + 32];

    for (int sl = wid; sl < SM1; sl += 8) {
        const float4* row = reinterpret_cast<const float4*>(selbase + (size_t)(sl + 1) * DD);
        float4 a0 = row[lane];
        float4 a1 = row[lane + 32];
        float dot = a0.x*q0.x + a0.y*q0.y + a0.z*q0.z + a0.w*q0.w
                  + a1.x*q1.x + a1.y*q1.y + a1.z*q1.z + a1.w*q1.w;
        float sq  = a0.x*a0.x + a0.y*a0.y + a0.z*a0.z + a0.w*a0.w
                  + a1.x*a1.x + a1.y*a1.y + a1.z*a1.z + a1.w*a1.w;
        #pragma unroll
        for (int o = 16; o; o >>= 1) {
            dot += __shfl_xor_sync(0xffffffffu, dot, o);
            sq  += __shfl_xor_sync(0xffffffffu, sq,  o);
        }
        if (lane == 0) {
            float sc = dot / fmaxf(sqrtf(sq), 1e-12f);
            bool valid = (rmbase[sl + 1] != 0) || (sl < KK);
            scores[sl] = valid ? sc : -CUDART_INF_F;
        }
    }
    __syncthreads();

    // ---- Phase 3: top-K by iterative argmax (tie-break: lowest index) ----
    for (int k = 0; k < KK; k++) {
        float v = (tid < SM1) ? scores[tid] : -CUDART_INF_F;
        int   ix = tid;
        #pragma unroll
        for (int o = 16; o; o >>= 1) {
            float ov = __shfl_xor_sync(0xffffffffu, v, o);
            int   oi = __shfl_xor_sync(0xffffffffu, ix, o);
            if (ov > v || (ov == v && oi < ix)) { v = ov; ix = oi; }
        }
        if (lane == 0) { red_val[wid] = v; red_idx[wid] = ix; }
        __syncthreads();
        if (tid == 0) {
            float bv = red_val[0]; int bi = red_idx[0];
            #pragma unroll
            for (int i = 1; i < 8; i++) {
                if (red_val[i] > bv || (red_val[i] == bv && red_idx[i] < bi)) {
                    bv = red_val[i]; bi = red_idx[i];
                }
            }
            sel_score[k] = bv;
            sel_idx[k]   = bi;
            scores[bi]   = -CUDART_INF_F;
        }
        __syncthreads();
    }

    // ---- Phase 4: softmax over selected scores (warp 0) ----
    if (wid == 0) {
        float s = (lane < KK) ? sel_score[lane] : -CUDART_INF_F;
        float m = s;
        #pragma unroll
        for (int o = 16; o; o >>= 1) m = fmaxf(m, __shfl_xor_sync(0xffffffffu, m, o));
        float e = (lane < KK) ? expf(s - m) : 0.f;
        float sum = e;
        #pragma unroll
        for (int o = 16; o; o >>= 1) sum += __shfl_xor_sync(0xffffffffu, sum, o);
        if (lane < KK) sw[lane] = e / sum;
    }
    __syncthreads();

    // ---- Phase 5: gather + scale + add segment; write outputs ----
    const float* txtbase = txt + (size_t)bh * SS * DD;
    const float* ambase  = am  + (size_t)bh * SS;
    float* terms = out_terms + (size_t)bh * KK * DD;
    const float4* sg = reinterpret_cast<const float4*>(sseg);
    const float4 g0 = sg[lane];
    const float4 g1 = sg[lane + 32];

    for (int k = wid; k < KK; k += 8) {
        int   id = sel_idx[k];
        float w  = sw[k];
        const float4* row = reinterpret_cast<const float4*>(txtbase + (size_t)(id + 1) * DD);
        float4* orow = reinterpret_cast<float4*>(terms + (size_t)k * DD);
        float4 a0 = row[lane];
        float4 a1 = row[lane + 32];
        float4 r0 = make_float4(fmaf(a0.x, w, g0.x), fmaf(a0.y, w, g0.y),
                                fmaf(a0.z, w, g0.z), fmaf(a0.w, w, g0.w));
        float4 r1 = make_float4(fmaf(a1.x, w, g1.x), fmaf(a1.y, w, g1.y),
                                fmaf(a1.z, w, g1.z), fmaf(a1.w, w, g1.w));
        orow[lane]      = r0;
        orow[lane + 32] = r1;
    }

    if (tid < KK) {
        int id = sel_idx[tid];
        out_mask[(size_t)bh * KK + tid] = ambase[id + 1];
        out_kid [(size_t)bh * KK + tid] = (float)id;
    }
}

extern "C" void kernel_launch(void* const* d_in, const int* in_sizes, int n_in,
                              void* d_out, int out_size) {
    const float* sel  = (const float*)d_in[0]; // news_selection_embedding
    const float* txt  = (const float*)d_in[1]; // news_embedding
    const float* user = (const float*)d_in[2]; // user_repr
    // d_in[3] = news_repr (unused by reference)
    const float* am   = (const float*)d_in[4]; // his_attn_mask
    const int*   rm   = (const int*)  d_in[5]; // his_refined_mask
    const float* seg  = (const float*)d_in[6]; // segment_embedding

    float* out = (float*)d_out;
    const size_t terms_elems = (size_t)BB * HH * KK * DD;   // 6,553,600
    const size_t mask_elems  = (size_t)BB * HH * KK;        // 25,600
    float* out_terms = out;
    float* out_mask  = out + terms_elems;
    float* out_kid   = out + terms_elems + mask_elems;

    dim3 grid(BB * HH);
    dim3 block(256);
    matching_reducer_kernel<<<grid, block>>>(sel, txt, user, am, rm, seg,
                                             out_terms, out_mask, out_kid);
}

// round 2
// speedup vs baseline: 1.0999x; 1.0999x over previous
#include <cuda_runtime.h>
#include <math_constants.h>

#define BB 16
#define HH 50
#define SS 256
#define DD 256
#define KK 32
#define SM1 (SS - 1)   // 255

__global__ __launch_bounds__(256, 4)
void matching_reducer_kernel(
    const float* __restrict__ sel,   // (B,H,S,D)
    const float* __restrict__ txt,   // (B,H,S,D)
    const float* __restrict__ user,  // (B,1,D)
    const float* __restrict__ am,    // (B,H,S)
    const int*   __restrict__ rm,    // (B,H,S)
    const float* __restrict__ seg,   // (H,1,D)
    float* __restrict__ out_terms,   // (B, H*K, D)
    float* __restrict__ out_mask,    // (B, H*K)
    float* __restrict__ out_kid)     // (B, H, K) as float
{
    const int bh   = blockIdx.x;
    const int b    = bh / HH;
    const int h    = bh % HH;
    const int tid  = threadIdx.x;
    const int wid  = tid >> 5;
    const int lane = tid & 31;

    __shared__ float qn[DD];
    __shared__ float sseg[DD];
    __shared__ float scores[SS];        // [0..254] scores, [255] = -inf pad
    __shared__ float sel_score[KK];
    __shared__ int   sel_idx[KK];
    __shared__ float sw[KK];
    __shared__ float wss[8];

    // ---- Phase 1: normalize user_repr[b]; stage segment embedding ----
    float qv = user[(size_t)b * DD + tid];
    sseg[tid] = seg[(size_t)h * DD + tid];
    if (tid == 0) scores[SM1] = -CUDART_INF_F;   // pad for top-K
    float ssq = qv * qv;
    #pragma unroll
    for (int o = 16; o; o >>= 1) ssq += __shfl_xor_sync(0xffffffffu, ssq, o);
    if (lane == 0) wss[wid] = ssq;
    __syncthreads();
    if (tid == 0) {
        float t = 0.f;
        #pragma unroll
        for (int i = 0; i < 8; i++) t += wss[i];
        wss[0] = 1.0f / fmaxf(sqrtf(t), 1e-12f);
    }
    __syncthreads();
    const float qscale = wss[0];
    qn[tid] = qv * qscale;
    __syncthreads();

    // ---- Phase 2: cosine scores, 4 rows per warp per pass (MLP=8) ----
    const float* selbase = sel + (size_t)bh * SS * DD;
    const int*   rmbase  = rm  + (size_t)bh * SS;
    const float4* q4 = reinterpret_cast<const float4*>(qn);
    const float4 q0 = q4[lane];
    const float4 q1 = q4[lane + 32];

    #pragma unroll
    for (int p = 0; p < 8; ++p) {
        const int r0 = p * 32 + wid * 4;   // first logical row (0-based in 0..254)
        float4 a[4][2];
        #pragma unroll
        for (int u = 0; u < 4; ++u) {
            const int slr = r0 + u;
            if (slr < SM1) {
                const float4* row = reinterpret_cast<const float4*>(
                    selbase + (size_t)(slr + 1) * DD);
                a[u][0] = __ldcs(row + lane);
                a[u][1] = __ldcs(row + lane + 32);
            }
        }
        #pragma unroll
        for (int u = 0; u < 4; ++u) {
            const int slr = r0 + u;
            if (slr < SM1) {
                float4 a0 = a[u][0], a1 = a[u][1];
                float dot = a0.x*q0.x + a0.y*q0.y + a0.z*q0.z + a0.w*q0.w
                          + a1.x*q1.x + a1.y*q1.y + a1.z*q1.z + a1.w*q1.w;
                float sq  = a0.x*a0.x + a0.y*a0.y + a0.z*a0.z + a0.w*a0.w
                          + a1.x*a1.x + a1.y*a1.y + a1.z*a1.z + a1.w*a1.w;
                #pragma unroll
                for (int o = 16; o; o >>= 1) {
                    dot += __shfl_xor_sync(0xffffffffu, dot, o);
                    sq  += __shfl_xor_sync(0xffffffffu, sq,  o);
                }
                if (lane == 0) {
                    float sc = dot / fmaxf(sqrtf(sq), 1e-12f);
                    bool valid = (rmbase[slr + 1] != 0) || (slr < KK);
                    scores[slr] = valid ? sc : -CUDART_INF_F;
                }
            }
        }
    }
    __syncthreads();

    // ---- Phase 3+4: barrier-free top-K + softmax, entirely in warp 0 ----
    if (wid == 0) {
        // each lane owns 8 scores: global idx = lane*8 + j
        float v[8];
        #pragma unroll
        for (int j = 0; j < 8; ++j) v[j] = scores[lane * 8 + j];

        for (int k = 0; k < KK; ++k) {
            // local argmax (ascending j scan + strict '>' keeps lowest index)
            float bv = v[0]; int bj = 0;
            #pragma unroll
            for (int j = 1; j < 8; ++j)
                if (v[j] > bv) { bv = v[j]; bj = j; }
            int gi = lane * 8 + bj;
            // warp argmax, tie-break lowest global index
            #pragma unroll
            for (int o = 16; o; o >>= 1) {
                float ov = __shfl_xor_sync(0xffffffffu, bv, o);
                int   oi = __shfl_xor_sync(0xffffffffu, gi, o);
                if (ov > bv || (ov == bv && oi < gi)) { bv = ov; gi = oi; }
            }
            if (lane == 0) { sel_score[k] = bv; sel_idx[k] = gi; }
            if ((gi >> 3) == lane) v[gi & 7] = -CUDART_INF_F;  // knock out winner
        }
        __syncwarp();
        // softmax over KK selected (sel_score[0] is the max — descending order)
        float s = sel_score[lane];            // lane < 32 == KK
        float m = sel_score[0];
        float e = expf(s - m);
        float sum = e;
        #pragma unroll
        for (int o = 16; o; o >>= 1) sum += __shfl_xor_sync(0xffffffffu, sum, o);
        sw[lane] = e / sum;
    }
    __syncthreads();

    // ---- Phase 5: gather + w*txt + seg, 4 rows per warp (loads first) ----
    const float* txtbase = txt + (size_t)bh * SS * DD;
    const float* ambase  = am  + (size_t)bh * SS;
    float* terms = out_terms + (size_t)bh * KK * DD;
    const float4* sg = reinterpret_cast<const float4*>(sseg);
    const float4 g0 = sg[lane];
    const float4 g1 = sg[lane + 32];

    {
        const int k0 = wid * 4;   // 8 warps * 4 = 32 = KK
        float4 a[4][2];
        float  w[4];
        #pragma unroll
        for (int u = 0; u < 4; ++u) {
            const int id = sel_idx[k0 + u];
            w[u] = sw[k0 + u];
            const float4* row = reinterpret_cast<const float4*>(
                txtbase + (size_t)(id + 1) * DD);
            a[u][0] = __ldcs(row + lane);
            a[u][1] = __ldcs(row + lane + 32);
        }
        #pragma unroll
        for (int u = 0; u < 4; ++u) {
            float4 a0 = a[u][0], a1 = a[u][1];
            float4 r0 = make_float4(fmaf(a0.x, w[u], g0.x), fmaf(a0.y, w[u], g0.y),
                                    fmaf(a0.z, w[u], g0.z), fmaf(a0.w, w[u], g0.w));
            float4 r1 = make_float4(fmaf(a1.x, w[u], g1.x), fmaf(a1.y, w[u], g1.y),
                                    fmaf(a1.z, w[u], g1.z), fmaf(a1.w, w[u], g1.w));
            float4* orow = reinterpret_cast<float4*>(terms + (size_t)(k0 + u) * DD);
            orow[lane]      = r0;
            orow[lane + 32] = r1;
        }
    }

    if (tid < KK) {
        int id = sel_idx[tid];
        out_mask[(size_t)bh * KK + tid] = ambase[id + 1];
        out_kid [(size_t)bh * KK + tid] = (float)id;
    }
}

extern "C" void kernel_launch(void* const* d_in, const int* in_sizes, int n_in,
                              void* d_out, int out_size) {
    const float* sel  = (const float*)d_in[0];
    const float* txt  = (const float*)d_in[1];
    const float* user = (const float*)d_in[2];
    // d_in[3] = news_repr (unused)
    const float* am   = (const float*)d_in[4];
    const int*   rm   = (const int*)  d_in[5];
    const float* seg  = (const float*)d_in[6];

    float* out = (float*)d_out;
    const size_t terms_elems = (size_t)BB * HH * KK * DD;
    const size_t mask_elems  = (size_t)BB * HH * KK;
    float* out_terms = out;
    float* out_mask  = out + terms_elems;
    float* out_kid   = out + terms_elems + mask_elems;

    matching_reducer_kernel<<<BB * HH, 256>>>(sel, txt, user, am, rm, seg,
                                              out_terms, out_mask, out_kid);
}

// round 3
// speedup vs baseline: 1.2453x; 1.1321x over previous
#include <cuda_runtime.h>
#include <math_constants.h>

#define BB 16
#define HH 50
#define SS 256
#define DD 256
#define KK 32
#define SM1 (SS - 1)   // 255

__global__ __launch_bounds__(128, 8)
void matching_reducer_kernel(
    const float* __restrict__ sel,   // (B,H,S,D)
    const float* __restrict__ txt,   // (B,H,S,D)
    const float* __restrict__ user,  // (B,1,D)
    const float* __restrict__ am,    // (B,H,S)
    const int*   __restrict__ rm,    // (B,H,S)
    const float* __restrict__ seg,   // (H,1,D)
    float* __restrict__ out_terms,   // (B, H*K, D)
    float* __restrict__ out_mask,    // (B, H*K)
    float* __restrict__ out_kid)     // (B, H, K) as float
{
    const int bh   = blockIdx.x;
    const int b    = bh / HH;
    const int h    = bh % HH;
    const int tid  = threadIdx.x;    // 0..127
    const int wid  = tid >> 5;       // 0..3
    const int lane = tid & 31;

    __shared__ float qn[DD];
    __shared__ float sseg[DD];
    __shared__ float scores[SS];     // [0..254] valid, [255] = -inf pad
    __shared__ float sel_score[KK];
    __shared__ int   sel_idx[KK];
    __shared__ float sw[KK];
    __shared__ float wss[4];

    // ---- Phase 1: normalize user_repr[b]; stage segment embedding ----
    float qa = user[(size_t)b * DD + tid];
    float qb = user[(size_t)b * DD + 128 + tid];
    sseg[tid]       = seg[(size_t)h * DD + tid];
    sseg[tid + 128] = seg[(size_t)h * DD + 128 + tid];
    if (tid == 0) scores[SM1] = -CUDART_INF_F;
    float ssq = qa * qa + qb * qb;
    #pragma unroll
    for (int o = 16; o; o >>= 1) ssq += __shfl_xor_sync(0xffffffffu, ssq, o);
    if (lane == 0) wss[wid] = ssq;
    __syncthreads();
    if (tid == 0) {
        float t = wss[0] + wss[1] + wss[2] + wss[3];
        wss[0] = 1.0f / fmaxf(sqrtf(t), 1e-12f);
    }
    __syncthreads();
    const float qscale = wss[0];
    qn[tid]       = qa * qscale;
    qn[tid + 128] = qb * qscale;
    __syncthreads();

    // ---- Phase 2: cosine scores, 4 rows per warp per pass ----
    const float* selbase = sel + (size_t)bh * SS * DD;
    const int*   rmbase  = rm  + (size_t)bh * SS;
    const float4* q4 = reinterpret_cast<const float4*>(qn);
    const float4 q0 = q4[lane];
    const float4 q1 = q4[lane + 32];

    #pragma unroll
    for (int p = 0; p < 16; ++p) {
        const int r0 = p * 16 + wid * 4;        // 0-based row in 0..254
        float4 a[4][2];
        #pragma unroll
        for (int u = 0; u < 4; ++u) {
            const int slr = r0 + u;
            if (slr < SM1) {
                const float4* row = reinterpret_cast<const float4*>(
                    selbase + (size_t)(slr + 1) * DD);
                a[u][0] = row[lane];
                a[u][1] = row[lane + 32];
            }
        }
        #pragma unroll
        for (int u = 0; u < 4; ++u) {
            const int slr = r0 + u;
            if (slr < SM1) {
                float4 a0 = a[u][0], a1 = a[u][1];
                float dot = a0.x*q0.x + a0.y*q0.y + a0.z*q0.z + a0.w*q0.w
                          + a1.x*q1.x + a1.y*q1.y + a1.z*q1.z + a1.w*q1.w;
                float sq  = a0.x*a0.x + a0.y*a0.y + a0.z*a0.z + a0.w*a0.w
                          + a1.x*a1.x + a1.y*a1.y + a1.z*a1.z + a1.w*a1.w;
                #pragma unroll
                for (int o = 16; o; o >>= 1) {
                    dot += __shfl_xor_sync(0xffffffffu, dot, o);
                    sq  += __shfl_xor_sync(0xffffffffu, sq,  o);
                }
                if (lane == 0) {
                    float sc = dot / fmaxf(sqrtf(sq), 1e-12f);
                    bool valid = (rmbase[slr + 1] != 0) || (slr < KK);
                    scores[slr] = valid ? sc : -CUDART_INF_F;
                }
            }
        }
    }
    __syncthreads();

    // ---- Phase 3+4: barrier-free top-K + softmax in warp 0 ----
    if (wid == 0) {
        float v[8];
        #pragma unroll
        for (int j = 0; j < 8; ++j) v[j] = scores[lane * 8 + j];

        for (int k = 0; k < KK; ++k) {
            float bv = v[0]; int bj = 0;
            #pragma unroll
            for (int j = 1; j < 8; ++j)
                if (v[j] > bv) { bv = v[j]; bj = j; }
            int gi = lane * 8 + bj;
            #pragma unroll
            for (int o = 16; o; o >>= 1) {
                float ov = __shfl_xor_sync(0xffffffffu, bv, o);
                int   oi = __shfl_xor_sync(0xffffffffu, gi, o);
                if (ov > bv || (ov == bv && oi < gi)) { bv = ov; gi = oi; }
            }
            if (lane == 0) { sel_score[k] = bv; sel_idx[k] = gi; }
            if ((gi >> 3) == lane) v[gi & 7] = -CUDART_INF_F;
        }
        __syncwarp();
        float s = sel_score[lane];     // KK == 32
        float m = sel_score[0];        // descending order -> max first
        float e = expf(s - m);
        float sum = e;
        #pragma unroll
        for (int o = 16; o; o >>= 1) sum += __shfl_xor_sync(0xffffffffu, sum, o);
        sw[lane] = e / sum;
    }
    __syncthreads();

    // ---- Phase 5: gather + w*txt + seg (8 rows per warp, 2 passes of 4) ----
    const float* txtbase = txt + (size_t)bh * SS * DD;
    const float* ambase  = am  + (size_t)bh * SS;
    float* terms = out_terms + (size_t)bh * KK * DD;
    const float4* sg = reinterpret_cast<const float4*>(sseg);
    const float4 g0 = sg[lane];
    const float4 g1 = sg[lane + 32];

    #pragma unroll
    for (int p = 0; p < 2; ++p) {
        const int k0 = p * 16 + wid * 4;       // 2 passes × 4 warps × 4 = 32
        float4 a[4][2];
        float  w[4];
        #pragma unroll
        for (int u = 0; u < 4; ++u) {
            const int id = sel_idx[k0 + u];
            w[u] = sw[k0 + u];
            const float4* row = reinterpret_cast<const float4*>(
                txtbase + (size_t)(id + 1) * DD);
            a[u][0] = __ldcs(row + lane);
            a[u][1] = __ldcs(row + lane + 32);
        }
        #pragma unroll
        for (int u = 0; u < 4; ++u) {
            float4 a0 = a[u][0], a1 = a[u][1];
            float4 r0 = make_float4(fmaf(a0.x, w[u], g0.x), fmaf(a0.y, w[u], g0.y),
                                    fmaf(a0.z, w[u], g0.z), fmaf(a0.w, w[u], g0.w));
            float4 r1 = make_float4(fmaf(a1.x, w[u], g1.x), fmaf(a1.y, w[u], g1.y),
                                    fmaf(a1.z, w[u], g1.z), fmaf(a1.w, w[u], g1.w));
            float4* orow = reinterpret_cast<float4*>(terms + (size_t)(k0 + u) * DD);
            orow[lane]      = r0;
            orow[lane + 32] = r1;
        }
    }

    if (tid < KK) {
        int id = sel_idx[tid];
        out_mask[(size_t)bh * KK + tid] = ambase[id + 1];
        out_kid [(size_t)bh * KK + tid] = (float)id;
    }
}

extern "C" void kernel_launch(void* const* d_in, const int* in_sizes, int n_in,
                              void* d_out, int out_size) {
    const float* sel  = (const float*)d_in[0];
    const float* txt  = (const float*)d_in[1];
    const float* user = (const float*)d_in[2];
    // d_in[3] = news_repr (unused)
    const float* am   = (const float*)d_in[4];
    const int*   rm   = (const int*)  d_in[5];
    const float* seg  = (const float*)d_in[6];

    float* out = (float*)d_out;
    const size_t terms_elems = (size_t)BB * HH * KK * DD;
    const size_t mask_elems  = (size_t)BB * HH * KK;
    float* out_terms = out;
    float* out_mask  = out + terms_elems;
    float* out_kid   = out + terms_elems + mask_elems;

    matching_reducer_kernel<<<BB * HH, 128>>>(sel, txt, user, am, rm, seg,
                                              out_terms, out_mask, out_kid);
}